// round 13
// baseline (speedup 1.0000x reference)
#include <cuda_runtime.h>
#include <cuda_fp16.h>

#define D        64
#define MAXN     100352           // padded to multiple of 1024 (scan chunks)
#define MAXE     1000000
#define CHUNK    1024
#define BN       128              // nodes per sage block
#define PAH      136              // smem pitch for fp16 A'/W' tiles (halves): 272B rows
#define PB       68               // pool staging pitch (floats)

static __device__ __forceinline__ unsigned pack_h2(float a, float b) {
    __half2 h = __floats2half2_rn(a, b);
    return *reinterpret_cast<unsigned*>(&h);
}
static __device__ __forceinline__ void ldsm4(unsigned* r, unsigned addr) {
    asm volatile("ldmatrix.sync.aligned.m8n8.x4.shared.b16 {%0,%1,%2,%3}, [%4];"
                 : "=r"(r[0]), "=r"(r[1]), "=r"(r[2]), "=r"(r[3]) : "r"(addr));
}
static __device__ __forceinline__ void mma16816(float* c, const unsigned* a,
                                                unsigned b0, unsigned b1) {
    asm volatile("mma.sync.aligned.m16n8k16.row.col.f32.f16.f16.f32 "
                 "{%0,%1,%2,%3}, {%4,%5,%6,%7}, {%8,%9}, {%0,%1,%2,%3};"
                 : "+f"(c[0]), "+f"(c[1]), "+f"(c[2]), "+f"(c[3])
                 : "r"(a[0]), "r"(a[1]), "r"(a[2]), "r"(a[3]), "r"(b0), "r"(b1));
}

// Static device scratch.
__device__ __half g_mean16[(size_t)MAXN * D];  // pre-scaled mean (fp16)
__device__ __half g_x16[(size_t)MAXN * D];
__device__ __half g_h16[(size_t)MAXN * D];
__device__ int    g_cnt[MAXN];
__device__ int    g_off[MAXN];
__device__ int    g_srcs[MAXE];
__device__ int    g_chunksum[128];
__device__ int    g_chunkbase[128];
__device__ float  g_rbc[64];
__device__ unsigned long long g_barc[8];   // generation barrier counters (monotonic)

// Grid-wide generation barrier (each block arrives exactly once per launch).
static __device__ __forceinline__ void gbar(int k, int nb) {
    __syncthreads();
    if (threadIdx.x == 0) {
        __threadfence();
        unsigned long long old = atomicAdd(&g_barc[k], 1ULL);
        unsigned long long target = (old / (unsigned long long)nb + 1ULL) * (unsigned long long)nb;
        while (*(volatile unsigned long long*)&g_barc[k] < target) {}
        __threadfence();
    }
    __syncthreads();
}

// ---------------------------------------------------------------------------
// MEGA-CSR kernel: zero+conv -> hist -> chunk scan -> top scan -> fill -> agg1
// All phases are high-occupancy (6 blocks/SM); grid barriers between phases.
// ---------------------------------------------------------------------------
__global__ __launch_bounds__(256, 6) void mega_csr_kernel(
    const int* __restrict__ src, const int* __restrict__ dst, int E,
    const float4* __restrict__ x4in, int n4,
    const int* __restrict__ batch, int N,
    float* __restrict__ out, int n_out,
    int n_pad, int nchunk, int NB)
{
    __shared__ int wsh[256];
    const int tid = threadIdx.x;
    const int bid = blockIdx.x;

    // ---- P0: zero g_cnt, zero out, convert x -> fp16, per-graph rbc ----
    {
        int total0 = (n_pad > n4) ? n_pad : n4;
        for (int i = bid * 256 + tid; i < total0; i += NB * 256) {
            if (i < n_pad) g_cnt[i] = 0;
            if (i < n_out) out[i] = 0.f;
            if (i < n4) {
                float4 v = __ldg(&x4in[i]);
                uint2 p;
                p.x = pack_h2(v.x, v.y);
                p.y = pack_h2(v.z, v.w);
                reinterpret_cast<uint2*>(g_x16)[i] = p;
            }
        }
        if (bid == 0 && tid < 64) {
            int b = tid;
            int lo0 = 0, hi = N;
            while (lo0 < hi) { int mid = (lo0 + hi) >> 1; if (__ldg(&batch[mid]) < b) lo0 = mid + 1; else hi = mid; }
            int lo1 = lo0; hi = N;
            while (lo1 < hi) { int mid = (lo1 + hi) >> 1; if (__ldg(&batch[mid]) < b + 1) lo1 = mid + 1; else hi = mid; }
            g_rbc[b] = 1.0f / fmaxf((float)(lo1 - lo0), 1.0f);
        }
    }
    gbar(0, NB);

    // ---- P1: in-degree histogram (int4, 4 edges/thread) ----
    {
        int hq = (E + 3) >> 2;
        for (int i = bid * 256 + tid; i < hq; i += NB * 256) {
            int e = i * 4;
            if (e + 4 <= E) {
                int4 d = __ldg(reinterpret_cast<const int4*>(dst) + i);
                atomicAdd(&g_cnt[d.x], 1);
                atomicAdd(&g_cnt[d.y], 1);
                atomicAdd(&g_cnt[d.z], 1);
                atomicAdd(&g_cnt[d.w], 1);
            } else {
                for (; e < E; e++) atomicAdd(&g_cnt[__ldg(&dst[e])], 1);
            }
        }
    }
    gbar(1, NB);

    // ---- P2: per-chunk exclusive scan (chunk-local) ----
    for (int c = bid; c < nchunk; c += NB) {
        int base = c * CHUNK + tid * 4;
        int4 cv = *reinterpret_cast<const int4*>(&g_cnt[base]);
        int s0 = cv.x, s1 = s0 + cv.y, s2 = s1 + cv.z, s3 = s2 + cv.w;
        wsh[tid] = s3;
        __syncthreads();
#pragma unroll
        for (int off = 1; off < 256; off <<= 1) {
            int v = (tid >= off) ? wsh[tid - off] : 0;
            __syncthreads();
            wsh[tid] += v;
            __syncthreads();
        }
        int excl = (tid > 0) ? wsh[tid - 1] : 0;
        int4 o;
        o.x = excl; o.y = excl + s0; o.z = excl + s1; o.w = excl + s2;
        *reinterpret_cast<int4*>(&g_off[base]) = o;
        if (tid == 255) g_chunksum[c] = wsh[255];
        __syncthreads();
    }
    gbar(2, NB);

    // ---- P3: block 0 scans chunk totals -> g_chunkbase ----
    if (bid == 0) {
        int v = 0;
        if (tid < 128 && tid < nchunk) v = g_chunksum[tid];
        if (tid < 128) wsh[tid] = v;
        __syncthreads();
#pragma unroll
        for (int off = 1; off < 128; off <<= 1) {
            int u = 0;
            if (tid < 128 && tid >= off) u = wsh[tid - off];
            __syncthreads();
            if (tid < 128) wsh[tid] += u;
            __syncthreads();
        }
        if (tid < 128) g_chunkbase[tid] = (tid > 0) ? wsh[tid - 1] : 0;
    }
    gbar(3, NB);

    // ---- P4: fill dst-sorted src list (scalar; latency-bound at high occ) ----
    for (int e = bid * 256 + tid; e < E; e += NB * 256) {
        int d = __ldg(&dst[e]);
        int p = atomicAdd(&g_off[d], 1) + __ldg(&g_chunkbase[d >> 10]);
        g_srcs[p] = __ldg(&src[e]);
    }
    gbar(4, NB);

    // ---- P5: layer-1 gather -> pre-scaled fp16 mean ----
    {
        const int lane = tid & 7;
        const unsigned gmask = 0xFFu << ((tid & 31) & ~7);
        const uint4* f4 = reinterpret_cast<const uint4*>(g_x16);
        for (int g0 = bid * 32; g0 < N; g0 += NB * 32) {
            int g = g0 + (tid >> 3);
            bool active = (g < N);
            int cnt = active ? g_cnt[g] : 0;
            int start = active ? (g_off[g] + __ldg(&g_chunkbase[g >> 10]) - cnt) : 0;
            float a[8];
#pragma unroll
            for (int c = 0; c < 8; c++) a[c] = 0.f;
            for (int i = 0; i < cnt; i += 8) {
                int my = (i + lane < cnt) ? __ldg(&g_srcs[start + i + lane]) : 0;
                int lim = cnt - i;
#pragma unroll
                for (int e = 0; e < 8; e++) {
                    if (e >= lim) break;
                    int s = __shfl_sync(gmask, my, e, 8);
                    uint4 v = __ldg(f4 + (size_t)s * 8 + lane);
                    float2 f0 = __half22float2(*reinterpret_cast<__half2*>(&v.x));
                    float2 f1 = __half22float2(*reinterpret_cast<__half2*>(&v.y));
                    float2 f2 = __half22float2(*reinterpret_cast<__half2*>(&v.z));
                    float2 f3 = __half22float2(*reinterpret_cast<__half2*>(&v.w));
                    a[0] += f0.x; a[1] += f0.y; a[2] += f1.x; a[3] += f1.y;
                    a[4] += f2.x; a[5] += f2.y; a[6] += f3.x; a[7] += f3.y;
                }
            }
            if (active) {
                float r = 1.0f / fmaxf((float)cnt, 1.0f);
                uint4 pk;
                pk.x = pack_h2(a[0] * r, a[1] * r);
                pk.y = pack_h2(a[2] * r, a[3] * r);
                pk.z = pack_h2(a[4] * r, a[5] * r);
                pk.w = pack_h2(a[6] * r, a[7] * r);
                reinterpret_cast<uint4*>(g_mean16)[(size_t)g * 8 + lane] = pk;
            }
        }
    }
}

// ---------------------------------------------------------------------------
// Gather aggregation kernel (layer 2): same scheme, separate launch.
// ---------------------------------------------------------------------------
__global__ __launch_bounds__(256) void agg_kernel(const __half* __restrict__ feat, int N) {
    int g = blockIdx.x * 32 + (threadIdx.x >> 3);
    int lane = threadIdx.x & 7;
    unsigned gmask = 0xFFu << ((threadIdx.x & 31) & ~7);
    bool active = (g < N);
    int cnt = active ? g_cnt[g] : 0;
    int start = active ? (g_off[g] + __ldg(&g_chunkbase[g >> 10]) - cnt) : 0;
    const uint4* f4 = reinterpret_cast<const uint4*>(feat);
    float a[8];
#pragma unroll
    for (int c = 0; c < 8; c++) a[c] = 0.f;

    for (int i = 0; i < cnt; i += 8) {
        int my = (i + lane < cnt) ? __ldg(&g_srcs[start + i + lane]) : 0;
        int lim = cnt - i;
#pragma unroll
        for (int e = 0; e < 8; e++) {
            if (e >= lim) break;
            int s = __shfl_sync(gmask, my, e, 8);
            uint4 v = __ldg(f4 + (size_t)s * 8 + lane);
            float2 f0 = __half22float2(*reinterpret_cast<__half2*>(&v.x));
            float2 f1 = __half22float2(*reinterpret_cast<__half2*>(&v.y));
            float2 f2 = __half22float2(*reinterpret_cast<__half2*>(&v.z));
            float2 f3 = __half22float2(*reinterpret_cast<__half2*>(&v.w));
            a[0] += f0.x; a[1] += f0.y; a[2] += f1.x; a[3] += f1.y;
            a[4] += f2.x; a[5] += f2.y; a[6] += f3.x; a[7] += f3.y;
        }
    }
    if (active) {
        float r = 1.0f / fmaxf((float)cnt, 1.0f);
        uint4 pk;
        pk.x = pack_h2(a[0] * r, a[1] * r);
        pk.y = pack_h2(a[2] * r, a[3] * r);
        pk.z = pack_h2(a[4] * r, a[5] * r);
        pk.w = pack_h2(a[6] * r, a[7] * r);
        reinterpret_cast<uint4*>(g_mean16)[(size_t)g * 8 + lane] = pk;
    }
}

// ---------------------------------------------------------------------------
// Tensor-core SAGE layer: out = act( [mean|x] @ [Wl|Wr]^T + b )
// ---------------------------------------------------------------------------
__global__ __launch_bounds__(256) void sage_kernel(const __half* __restrict__ xin16,
                                                   const float* __restrict__ Wl,
                                                   const float* __restrict__ bl,
                                                   const float* __restrict__ Wr,
                                                   __half* __restrict__ hout16,
                                                   const int* __restrict__ batch,
                                                   float* __restrict__ pool_out,
                                                   int N, int do_pool) {
    extern __shared__ char smraw[];
    __half* sA   = reinterpret_cast<__half*>(smraw);                 // 128 x PAH halves
    __half* sW   = sA + 128 * PAH;                                   // 64 x PAH halves
    float*  sRbc = reinterpret_cast<float*>(sW + 64 * PAH);          // 64
    int*    sBat = reinterpret_cast<int*>(sRbc + 64);                // 128
    float*  pb   = reinterpret_cast<float*>(smraw);                  // pool reuse: 128 x PB

    const int tid  = threadIdx.x;
    const int base = blockIdx.x * BN;

    if (do_pool) {
        if (tid < BN) {
            int node = base + tid;
            sBat[tid] = (node < N) ? __ldg(&batch[node]) : 0;
        }
        if (tid >= BN && tid < BN + 64) sRbc[tid - BN] = g_rbc[tid - BN];
    }

    const uint4* m4 = reinterpret_cast<const uint4*>(g_mean16);
    const uint4* x4 = reinterpret_cast<const uint4*>(xin16);
    const uint4 z4 = make_uint4(0u, 0u, 0u, 0u);
    for (int i = tid; i < 2 * BN * 8; i += 256) {
        int half2nd = (i >= BN * 8);
        int ii = i - half2nd * BN * 8;
        int n = ii >> 3, q = ii & 7;
        int node = base + n;
        uint4 v = z4;
        if (node < N)
            v = half2nd ? __ldg(&x4[(size_t)node * 8 + q])
                        : __ldg(&m4[(size_t)node * 8 + q]);
        *reinterpret_cast<uint4*>(&sA[n * PAH + half2nd * 64 + q * 8]) = v;
    }
    for (int i = tid; i < 2048; i += 256) {
        int half2nd = (i >= 1024);
        int ii = i - half2nd * 1024;
        int j = ii >> 4, kq = ii & 15;
        float4 v = half2nd ? __ldg(reinterpret_cast<const float4*>(&Wr[j * 64 + kq * 4]))
                           : __ldg(reinterpret_cast<const float4*>(&Wl[j * 64 + kq * 4]));
        uint2 p;
        p.x = pack_h2(v.x, v.y);
        p.y = pack_h2(v.z, v.w);
        *reinterpret_cast<uint2*>(&sW[j * PAH + half2nd * 64 + kq * 4]) = p;
    }
    __syncthreads();

    const int l  = tid & 31;
    const int w  = tid >> 5;
    const int m0 = w * 16;

    unsigned sAb = (unsigned)__cvta_generic_to_shared(sA);
    unsigned sWb = (unsigned)__cvta_generic_to_shared(sW);
    unsigned aAddr = sAb + (unsigned)((m0 + (l & 15)) * (PAH * 2) + (l >> 4) * 16);
    unsigned bAddr = sWb + (unsigned)((((l & 7) + ((l >> 4) << 3)) * (PAH * 2)) + ((l >> 3) & 1) * 16);

    float acc[8][4];
#pragma unroll
    for (int nt = 0; nt < 8; nt++)
#pragma unroll
        for (int c = 0; c < 4; c++) acc[nt][c] = 0.f;

#pragma unroll
    for (int ks = 0; ks < 8; ks++) {
        unsigned a[4];
        ldsm4(a, aAddr + ks * 32);
#pragma unroll
        for (int np = 0; np < 4; np++) {
            unsigned t[4];
            ldsm4(t, bAddr + np * (16 * PAH * 2) + ks * 32);
            mma16816(acc[2 * np],     a, t[0], t[1]);
            mma16816(acc[2 * np + 1], a, t[2], t[3]);
        }
    }

    const int c2 = (l & 3) * 2;
    const int r0 = m0 + (l >> 2);
    const int r1 = r0 + 8;

    if (!do_pool) {
#pragma unroll
        for (int nt = 0; nt < 8; nt++) {
            int col = nt * 8 + c2;
            float b0 = __ldg(&bl[col]), b1 = __ldg(&bl[col + 1]);
            int node0 = base + r0;
            int node1 = base + r1;
            if (node0 < N) {
                unsigned p = pack_h2(fmaxf(acc[nt][0] + b0, 0.f),
                                     fmaxf(acc[nt][1] + b1, 0.f));
                *reinterpret_cast<unsigned*>(&hout16[(size_t)node0 * 64 + col]) = p;
            }
            if (node1 < N) {
                unsigned p = pack_h2(fmaxf(acc[nt][2] + b0, 0.f),
                                     fmaxf(acc[nt][3] + b1, 0.f));
                *reinterpret_cast<unsigned*>(&hout16[(size_t)node1 * 64 + col]) = p;
            }
        }
    } else {
        __syncthreads();
#pragma unroll
        for (int nt = 0; nt < 8; nt++) {
            int col = nt * 8 + c2;
            float b0 = __ldg(&bl[col]), b1 = __ldg(&bl[col + 1]);
            float2 v0, v1;
            v0.x = (base + r0 < N) ? acc[nt][0] + b0 : 0.f;
            v0.y = (base + r0 < N) ? acc[nt][1] + b1 : 0.f;
            v1.x = (base + r1 < N) ? acc[nt][2] + b0 : 0.f;
            v1.y = (base + r1 < N) ? acc[nt][3] + b1 : 0.f;
            *reinterpret_cast<float2*>(&pb[r0 * PB + col]) = v0;
            *reinterpret_cast<float2*>(&pb[r1 * PB + col]) = v1;
        }
        __syncthreads();
        if (tid < 64) {
            const int j = tid;
            int cur = sBat[0];
            float sum = 0.f;
#pragma unroll 4
            for (int n = 0; n < BN; n++) {
                int b = sBat[n];
                if (b != cur) {
                    atomicAdd(&pool_out[cur * 64 + j], sum * sRbc[cur]);
                    sum = 0.f;
                    cur = b;
                }
                sum += pb[n * PB + j];
            }
            atomicAdd(&pool_out[cur * 64 + j], sum * sRbc[cur]);
        }
    }
}

// ---------------------------------------------------------------------------
// kernel_launch
// Inputs: x, edge_index, edge_attr, batch, edge_emb,
//         W1_l, b1_l, W1_r, W2_l, b2_l, W2_r
// ---------------------------------------------------------------------------
extern "C" void kernel_launch(void* const* d_in, const int* in_sizes, int n_in,
                              void* d_out, int out_size) {
    const float* x     = (const float*)d_in[0];
    const int*   eidx  = (const int*)d_in[1];
    const int*   batch = (const int*)d_in[3];
    const float* W1l   = (const float*)d_in[5];
    const float* b1l   = (const float*)d_in[6];
    const float* W1r   = (const float*)d_in[7];
    const float* W2l   = (const float*)d_in[8];
    const float* b2l   = (const float*)d_in[9];
    const float* W2r   = (const float*)d_in[10];
    float*       out   = (float*)d_out;

    const int N = in_sizes[3];
    const int E = in_sizes[1] / 2;
    const int* src = eidx;
    const int* dst = eidx + E;

    void* xp = nullptr; void* hp = nullptr;
    cudaGetSymbolAddress(&xp, g_x16);
    cudaGetSymbolAddress(&hp, g_h16);
    __half* x16 = (__half*)xp;
    __half* h16 = (__half*)hp;

    const int smem = (128 + 64) * PAH * (int)sizeof(__half)
                     + 64 * (int)sizeof(float) + BN * (int)sizeof(int);
    cudaFuncSetAttribute(sage_kernel, cudaFuncAttributeMaxDynamicSharedMemorySize, smem);

    int nsm = 0;
    cudaDeviceGetAttribute(&nsm, cudaDevAttrMultiProcessorCount, 0);
    if (nsm <= 0) nsm = 148;
    int maxb = 0;
    cudaOccupancyMaxActiveBlocksPerMultiprocessor(&maxb, mega_csr_kernel, 256, 0);
    if (maxb < 1) maxb = 1;
    if (maxb > 6) maxb = 6;
    const int NB = nsm * maxb;      // guaranteed-resident grid

    const int nchunk = (N + CHUNK - 1) / CHUNK;
    const int n_pad  = nchunk * CHUNK;
    const int n4     = N * 16;
    const int ablk   = (N + 31) / 32;
    const int gblk   = (N + BN - 1) / BN;

    // CSR build + conversion + layer-1 gather (one persistent launch)
    mega_csr_kernel<<<NB, 256>>>(src, dst, E,
                                 reinterpret_cast<const float4*>(x), n4,
                                 batch, N, out, out_size, n_pad, nchunk, NB);

    // Layer 1 GEMM
    sage_kernel<<<gblk, 256, smem>>>(x16, W1l, b1l, W1r, h16, nullptr, nullptr, N, 0);

    // Layer 2 gather + GEMM + fused scaled pool
    agg_kernel<<<ablk, 256>>>(h16, N);
    sage_kernel<<<gblk, 256, smem>>>(h16, W2l, b2l, W2r, nullptr, batch, out, N, 1);
}

// round 15
// speedup vs baseline: 1.2066x; 1.2066x over previous
#include <cuda_runtime.h>
#include <cuda_fp16.h>

#define D        64
#define MAXN     100352           // padded to multiple of 1024 (scan chunks)
#define MAXE     1000000
#define CHUNK    1024
#define BN       128              // nodes per sage block
#define PAH      136              // smem pitch for fp16 A'/W' tiles (halves): 272B rows
#define PB       68               // pool staging pitch (floats)

static __device__ __forceinline__ unsigned pack_h2(float a, float b) {
    __half2 h = __floats2half2_rn(a, b);
    return *reinterpret_cast<unsigned*>(&h);
}
static __device__ __forceinline__ void ldsm4(unsigned* r, unsigned addr) {
    asm volatile("ldmatrix.sync.aligned.m8n8.x4.shared.b16 {%0,%1,%2,%3}, [%4];"
                 : "=r"(r[0]), "=r"(r[1]), "=r"(r[2]), "=r"(r[3]) : "r"(addr));
}
static __device__ __forceinline__ void mma16816(float* c, const unsigned* a,
                                                unsigned b0, unsigned b1) {
    asm volatile("mma.sync.aligned.m16n8k16.row.col.f32.f16.f16.f32 "
                 "{%0,%1,%2,%3}, {%4,%5,%6,%7}, {%8,%9}, {%0,%1,%2,%3};"
                 : "+f"(c[0]), "+f"(c[1]), "+f"(c[2]), "+f"(c[3])
                 : "r"(a[0]), "r"(a[1]), "r"(a[2]), "r"(a[3]), "r"(b0), "r"(b1));
}
// cp.async 16B with zero-fill when src_size==0.
static __device__ __forceinline__ void cpa16(unsigned saddr, const void* gptr, int src_size) {
    asm volatile("cp.async.ca.shared.global [%0], [%1], 16, %2;"
                 :: "r"(saddr), "l"(gptr), "r"(src_size));
}
static __device__ __forceinline__ void cpa_commit_wait() {
    asm volatile("cp.async.commit_group;");
    asm volatile("cp.async.wait_group 0;" ::: "memory");
}

// Static device scratch.
__device__ __half g_mean16[(size_t)MAXN * D];  // pre-scaled mean (fp16)
__device__ __half g_x16[(size_t)MAXN * D];
__device__ __half g_h16[(size_t)MAXN * D];
__device__ __half g_w1[64 * 128];              // pre-converted [Wl|Wr] layer 1, [j][128]
__device__ __half g_w2[64 * 128];              // layer 2
__device__ int    g_cnt[MAXN];
__device__ int    g_off[MAXN];
__device__ int    g_srcs[MAXE];
__device__ int    g_chunksum[128];
__device__ int    g_chunkbase[128];
__device__ int    g_done;
__device__ float  g_rbc[64];       // 1/max(count(batch==b),1)

// ---------------------------------------------------------------------------
// k0: zero histogram/flags/pool output, pre-convert W1/W2 to fp16, rbc.
// ---------------------------------------------------------------------------
__global__ __launch_bounds__(256) void zero_kernel(int n_pad, float* __restrict__ out,
                                                   int n_out, const int* __restrict__ batch,
                                                   int N,
                                                   const float4* __restrict__ W1l4,
                                                   const float4* __restrict__ W1r4,
                                                   const float4* __restrict__ W2l4,
                                                   const float4* __restrict__ W2r4) {
    int i = blockIdx.x * 256 + threadIdx.x;
    if (i < n_pad) g_cnt[i] = 0;
    if (i < n_out) out[i] = 0.f;
    if (i == 0) g_done = 0;
    if (i < 4096) {
        int layer = i >> 11;            // 0: W1, 1: W2
        int ii = i & 2047;
        int half2nd = (ii >= 1024);
        int jj = ii & 1023;
        int j = jj >> 4, kq = jj & 15;  // row j, float4 index kq
        const float4* srcm = layer ? (half2nd ? W2r4 : W2l4)
                                   : (half2nd ? W1r4 : W1l4);
        float4 v = __ldg(&srcm[j * 16 + kq]);
        uint2 p;
        p.x = pack_h2(v.x, v.y);
        p.y = pack_h2(v.z, v.w);
        __half* dst = layer ? g_w2 : g_w1;
        *reinterpret_cast<uint2*>(&dst[j * 128 + half2nd * 64 + kq * 4]) = p;
    }
    if (blockIdx.x == 0 && threadIdx.x < 64) {
        int b = threadIdx.x;
        int lo0 = 0, hi = N;
        while (lo0 < hi) { int mid = (lo0 + hi) >> 1; if (__ldg(&batch[mid]) < b) lo0 = mid + 1; else hi = mid; }
        int lo1 = lo0; hi = N;
        while (lo1 < hi) { int mid = (lo1 + hi) >> 1; if (__ldg(&batch[mid]) < b + 1) lo1 = mid + 1; else hi = mid; }
        g_rbc[b] = 1.0f / fmaxf((float)(lo1 - lo0), 1.0f);
    }
}

// ---------------------------------------------------------------------------
// k1: in-degree histogram over dst (int4 loads) FUSED with x -> fp16 convert.
// ---------------------------------------------------------------------------
__global__ __launch_bounds__(256) void hist_conv_kernel(const int* __restrict__ dst, int E,
                                                        const float4* __restrict__ x4,
                                                        int n4) {
    int i = blockIdx.x * 256 + threadIdx.x;
    int hq = (E + 3) >> 2;
    if (i < hq) {
        int e = i * 4;
        if (e + 4 <= E) {
            int4 d = __ldg(reinterpret_cast<const int4*>(dst) + i);
            atomicAdd(&g_cnt[d.x], 1);
            atomicAdd(&g_cnt[d.y], 1);
            atomicAdd(&g_cnt[d.z], 1);
            atomicAdd(&g_cnt[d.w], 1);
        } else {
            for (; e < E; e++) atomicAdd(&g_cnt[__ldg(&dst[e])], 1);
        }
    }
    if (i < n4) {
        float4 v = __ldg(&x4[i]);
        uint2 p;
        p.x = pack_h2(v.x, v.y);
        p.y = pack_h2(v.z, v.w);
        reinterpret_cast<uint2*>(g_x16)[i] = p;
    }
}

// ---------------------------------------------------------------------------
// k2: per-chunk (1024) exclusive scan of g_cnt -> g_off (chunk-local); last
// block scans the chunk totals into g_chunkbase (decoupled via g_done).
// ---------------------------------------------------------------------------
__global__ __launch_bounds__(256) void scan_chunk_kernel() {
    __shared__ int w[256];
    __shared__ int isLast;
    int t = threadIdx.x;
    int base = blockIdx.x * CHUNK + t * 4;
    int4 c = *reinterpret_cast<const int4*>(&g_cnt[base]);
    int s0 = c.x, s1 = s0 + c.y, s2 = s1 + c.z, s3 = s2 + c.w;
    w[t] = s3;
    __syncthreads();
#pragma unroll
    for (int off = 1; off < 256; off <<= 1) {
        int v = (t >= off) ? w[t - off] : 0;
        __syncthreads();
        w[t] += v;
        __syncthreads();
    }
    int excl = (t > 0) ? w[t - 1] : 0;
    int4 o;
    o.x = excl; o.y = excl + s0; o.z = excl + s1; o.w = excl + s2;
    *reinterpret_cast<int4*>(&g_off[base]) = o;
    if (t == 255) g_chunksum[blockIdx.x] = w[255];

    __threadfence();
    if (t == 0) isLast = (atomicAdd(&g_done, 1) == (int)gridDim.x - 1);
    __syncthreads();
    if (isLast) {
        int v = 0;
        if (t < 128 && t < (int)gridDim.x)
            v = *((volatile int*)&g_chunksum[t]);
        if (t < 128) w[t] = v;
        __syncthreads();
#pragma unroll
        for (int off = 1; off < 128; off <<= 1) {
            int u = 0;
            if (t < 128 && t >= off) u = w[t - off];
            __syncthreads();
            if (t < 128) w[t] += u;
            __syncthreads();
        }
        if (t < 128) g_chunkbase[t] = (t > 0) ? w[t - 1] : 0;
    }
}

// ---------------------------------------------------------------------------
// k3: fill dst-sorted src list (scalar; latency-bound, max occupancy).
// ---------------------------------------------------------------------------
__global__ __launch_bounds__(256) void fill_kernel(const int* __restrict__ src,
                                                   const int* __restrict__ dst, int E) {
    int e = blockIdx.x * 256 + threadIdx.x;
    if (e >= E) return;
    int d = __ldg(&dst[e]);
    int p = atomicAdd(&g_off[d], 1) + __ldg(&g_chunkbase[d >> 10]);
    g_srcs[p] = __ldg(&src[e]);
}

// ---------------------------------------------------------------------------
// Gather aggregation (fp16 payload): 8 threads per dst node, shuffle-broadcast
// edge indices, fp32 accumulation, writes PRE-SCALED fp16 mean.
// ---------------------------------------------------------------------------
__global__ __launch_bounds__(256) void agg_kernel(const __half* __restrict__ feat, int N) {
    int g = blockIdx.x * 32 + (threadIdx.x >> 3);
    int lane = threadIdx.x & 7;
    unsigned gmask = 0xFFu << ((threadIdx.x & 31) & ~7);
    bool active = (g < N);
    int cnt = active ? g_cnt[g] : 0;
    int start = active ? (g_off[g] + __ldg(&g_chunkbase[g >> 10]) - cnt) : 0;
    const uint4* f4 = reinterpret_cast<const uint4*>(feat);
    float a[8];
#pragma unroll
    for (int c = 0; c < 8; c++) a[c] = 0.f;

    for (int i = 0; i < cnt; i += 8) {
        int my = (i + lane < cnt) ? __ldg(&g_srcs[start + i + lane]) : 0;
        int lim = cnt - i;
#pragma unroll
        for (int e = 0; e < 8; e++) {
            if (e >= lim) break;
            int s = __shfl_sync(gmask, my, e, 8);
            uint4 v = __ldg(f4 + (size_t)s * 8 + lane);
            float2 f0 = __half22float2(*reinterpret_cast<__half2*>(&v.x));
            float2 f1 = __half22float2(*reinterpret_cast<__half2*>(&v.y));
            float2 f2 = __half22float2(*reinterpret_cast<__half2*>(&v.z));
            float2 f3 = __half22float2(*reinterpret_cast<__half2*>(&v.w));
            a[0] += f0.x; a[1] += f0.y; a[2] += f1.x; a[3] += f1.y;
            a[4] += f2.x; a[5] += f2.y; a[6] += f3.x; a[7] += f3.y;
        }
    }
    if (active) {
        float r = 1.0f / fmaxf((float)cnt, 1.0f);
        uint4 pk;
        pk.x = pack_h2(a[0] * r, a[1] * r);
        pk.y = pack_h2(a[2] * r, a[3] * r);
        pk.z = pack_h2(a[4] * r, a[5] * r);
        pk.w = pack_h2(a[6] * r, a[7] * r);
        reinterpret_cast<uint4*>(g_mean16)[(size_t)g * 8 + lane] = pk;
    }
}

// ---------------------------------------------------------------------------
// Tensor-core SAGE layer with cp.async staging (no conversions in staging).
// out = act( [mean|x] @ [Wl|Wr]^T + b ), Wc pre-converted fp16 [j][128].
// ---------------------------------------------------------------------------
__global__ __launch_bounds__(256) void sage_kernel(const __half* __restrict__ xin16,
                                                   const __half* __restrict__ Wc,
                                                   const float* __restrict__ bl,
                                                   __half* __restrict__ hout16,
                                                   const int* __restrict__ batch,
                                                   float* __restrict__ pool_out,
                                                   int N, int do_pool) {
    extern __shared__ char smraw[];
    __half* sA   = reinterpret_cast<__half*>(smraw);                 // 128 x PAH halves
    __half* sW   = sA + 128 * PAH;                                   // 64 x PAH halves
    float*  sRbc = reinterpret_cast<float*>(sW + 64 * PAH);          // 64
    int*    sBat = reinterpret_cast<int*>(sRbc + 64);                // 128
    float*  pb   = reinterpret_cast<float*>(smraw);                  // pool reuse: 128 x PB

    const int tid  = threadIdx.x;
    const int base = blockIdx.x * BN;
    unsigned sAb = (unsigned)__cvta_generic_to_shared(sA);
    unsigned sWb = (unsigned)__cvta_generic_to_shared(sW);

    // --- async staging ---
    // A' = [mean16 | x16]: 2048 chunks of 16B (128 rows x 16 chunks).
#pragma unroll
    for (int r = 0; r < 8; r++) {
        int i = r * 256 + tid;
        int half2nd = (i >= BN * 8);
        int ii = i - half2nd * BN * 8;
        int n = ii >> 3, q = ii & 7;          // q in 0..7 covers 64 halves (one half-row)
        int node = base + n;
        const __half* srcbuf = half2nd ? xin16 : g_mean16;
        const void* gp = srcbuf + ((size_t)(node < N ? node : 0) * 64 + q * 8);
        cpa16(sAb + (unsigned)((n * PAH + half2nd * 64 + q * 8) * 2), gp,
              (node < N) ? 16 : 0);
    }
    // W': 1024 chunks of 16B (64 rows x 16 chunks of the 128-half row).
#pragma unroll
    for (int r = 0; r < 4; r++) {
        int c = r * 256 + tid;
        int j = c >> 4, q = c & 15;           // q in 0..15 covers 128 halves
        cpa16(sWb + (unsigned)((j * PAH + q * 8) * 2), Wc + j * 128 + q * 8, 16);
    }

    if (do_pool) {
        if (tid < BN) {
            int node = base + tid;
            sBat[tid] = (node < N) ? __ldg(&batch[node]) : 0;
        }
        if (tid >= BN && tid < BN + 64) sRbc[tid - BN] = g_rbc[tid - BN];
    }

    cpa_commit_wait();
    __syncthreads();

    const int l  = tid & 31;
    const int w  = tid >> 5;
    const int m0 = w * 16;

    unsigned aAddr = sAb + (unsigned)((m0 + (l & 15)) * (PAH * 2) + (l >> 4) * 16);
    unsigned bAddr = sWb + (unsigned)((((l & 7) + ((l >> 4) << 3)) * (PAH * 2)) + ((l >> 3) & 1) * 16);

    float acc[8][4];
#pragma unroll
    for (int nt = 0; nt < 8; nt++)
#pragma unroll
        for (int c = 0; c < 4; c++) acc[nt][c] = 0.f;

#pragma unroll
    for (int ks = 0; ks < 8; ks++) {
        unsigned a[4];
        ldsm4(a, aAddr + ks * 32);
#pragma unroll
        for (int np = 0; np < 4; np++) {
            unsigned t[4];
            ldsm4(t, bAddr + np * (16 * PAH * 2) + ks * 32);
            mma16816(acc[2 * np],     a, t[0], t[1]);
            mma16816(acc[2 * np + 1], a, t[2], t[3]);
        }
    }

    const int c2 = (l & 3) * 2;
    const int r0 = m0 + (l >> 2);
    const int r1 = r0 + 8;

    if (!do_pool) {
#pragma unroll
        for (int nt = 0; nt < 8; nt++) {
            int col = nt * 8 + c2;
            float b0 = __ldg(&bl[col]), b1 = __ldg(&bl[col + 1]);
            int node0 = base + r0;
            int node1 = base + r1;
            if (node0 < N) {
                unsigned p = pack_h2(fmaxf(acc[nt][0] + b0, 0.f),
                                     fmaxf(acc[nt][1] + b1, 0.f));
                *reinterpret_cast<unsigned*>(&hout16[(size_t)node0 * 64 + col]) = p;
            }
            if (node1 < N) {
                unsigned p = pack_h2(fmaxf(acc[nt][2] + b0, 0.f),
                                     fmaxf(acc[nt][3] + b1, 0.f));
                *reinterpret_cast<unsigned*>(&hout16[(size_t)node1 * 64 + col]) = p;
            }
        }
    } else {
        __syncthreads();  // done with sA region; reuse as pool buffer
#pragma unroll
        for (int nt = 0; nt < 8; nt++) {
            int col = nt * 8 + c2;
            float b0 = __ldg(&bl[col]), b1 = __ldg(&bl[col + 1]);
            float2 v0, v1;
            v0.x = (base + r0 < N) ? acc[nt][0] + b0 : 0.f;
            v0.y = (base + r0 < N) ? acc[nt][1] + b1 : 0.f;
            v1.x = (base + r1 < N) ? acc[nt][2] + b0 : 0.f;
            v1.y = (base + r1 < N) ? acc[nt][3] + b1 : 0.f;
            *reinterpret_cast<float2*>(&pb[r0 * PB + col]) = v0;
            *reinterpret_cast<float2*>(&pb[r1 * PB + col]) = v1;
        }
        __syncthreads();
        if (tid < 64) {
            const int j = tid;
            int cur = sBat[0];
            float sum = 0.f;
#pragma unroll 4
            for (int n = 0; n < BN; n++) {
                int b = sBat[n];
                if (b != cur) {
                    atomicAdd(&pool_out[cur * 64 + j], sum * sRbc[cur]);
                    sum = 0.f;
                    cur = b;
                }
                sum += pb[n * PB + j];
            }
            atomicAdd(&pool_out[cur * 64 + j], sum * sRbc[cur]);
        }
    }
}

// ---------------------------------------------------------------------------
// kernel_launch
// Inputs: x, edge_index, edge_attr, batch, edge_emb,
//         W1_l, b1_l, W1_r, W2_l, b2_l, W2_r
// ---------------------------------------------------------------------------
extern "C" void kernel_launch(void* const* d_in, const int* in_sizes, int n_in,
                              void* d_out, int out_size) {
    const float* x     = (const float*)d_in[0];
    const int*   eidx  = (const int*)d_in[1];
    const int*   batch = (const int*)d_in[3];
    const float* W1l   = (const float*)d_in[5];
    const float* b1l   = (const float*)d_in[6];
    const float* W1r   = (const float*)d_in[7];
    const float* W2l   = (const float*)d_in[8];
    const float* b2l   = (const float*)d_in[9];
    const float* W2r   = (const float*)d_in[10];
    float*       out   = (float*)d_out;

    const int N = in_sizes[3];
    const int E = in_sizes[1] / 2;
    const int* src = eidx;
    const int* dst = eidx + E;

    void* xp = nullptr; void* hp = nullptr; void* w1p = nullptr; void* w2p = nullptr;
    cudaGetSymbolAddress(&xp, g_x16);
    cudaGetSymbolAddress(&hp, g_h16);
    cudaGetSymbolAddress(&w1p, g_w1);
    cudaGetSymbolAddress(&w2p, g_w2);
    __half* x16 = (__half*)xp;
    __half* h16 = (__half*)hp;
    __half* w1c = (__half*)w1p;
    __half* w2c = (__half*)w2p;

    const int smem = (128 + 64) * PAH * (int)sizeof(__half)
                     + 64 * (int)sizeof(float) + BN * (int)sizeof(int);
    cudaFuncSetAttribute(sage_kernel, cudaFuncAttributeMaxDynamicSharedMemorySize, smem);

    const int nchunk = (N + CHUNK - 1) / CHUNK;
    const int n_pad  = nchunk * CHUNK;
    const int n4     = N * 16;
    const int zb     = (n_pad + 255) / 256;
    const int hq     = (E + 3) / 4;
    const int hcb    = (max(hq, n4) + 255) / 256;
    const int eblk   = (E + 255) / 256;
    const int ablk   = (N + 31) / 32;
    const int gblk   = (N + BN - 1) / BN;

    // CSR build + conversions (once; reused by both layers)
    zero_kernel<<<zb, 256>>>(n_pad, out, out_size, batch, N,
                             reinterpret_cast<const float4*>(W1l),
                             reinterpret_cast<const float4*>(W1r),
                             reinterpret_cast<const float4*>(W2l),
                             reinterpret_cast<const float4*>(W2r));
    hist_conv_kernel<<<hcb, 256>>>(dst, E, reinterpret_cast<const float4*>(x), n4);
    scan_chunk_kernel<<<nchunk, 256>>>();
    fill_kernel<<<eblk, 256>>>(src, dst, E);

    // Layer 1
    agg_kernel<<<ablk, 256>>>(x16, N);
    sage_kernel<<<gblk, 256, smem>>>(x16, w1c, b1l, h16, nullptr, nullptr, N, 0);

    // Layer 2 + fused scaled pool
    agg_kernel<<<ablk, 256>>>(h16, N);
    sage_kernel<<<gblk, 256, smem>>>(h16, w2c, b2l, nullptr, batch, out, N, 1);
}

// round 16
// speedup vs baseline: 1.2417x; 1.0291x over previous
#include <cuda_runtime.h>
#include <cuda_fp16.h>

#define D        64
#define MAXN     100352           // padded to multiple of 1024 (scan chunks)
#define MAXE     1000000
#define CHUNK    1024
#define BN       128              // nodes per sage block
#define PAH      136              // smem pitch for fp16 A'/W' tiles (halves): 272B rows
#define PB       68               // pool staging pitch (floats)

static __device__ __forceinline__ unsigned pack_h2(float a, float b) {
    __half2 h = __floats2half2_rn(a, b);
    return *reinterpret_cast<unsigned*>(&h);
}
static __device__ __forceinline__ void ldsm4(unsigned* r, unsigned addr) {
    asm volatile("ldmatrix.sync.aligned.m8n8.x4.shared.b16 {%0,%1,%2,%3}, [%4];"
                 : "=r"(r[0]), "=r"(r[1]), "=r"(r[2]), "=r"(r[3]) : "r"(addr));
}
static __device__ __forceinline__ void mma16816(float* c, const unsigned* a,
                                                unsigned b0, unsigned b1) {
    asm volatile("mma.sync.aligned.m16n8k16.row.col.f32.f16.f16.f32 "
                 "{%0,%1,%2,%3}, {%4,%5,%6,%7}, {%8,%9}, {%0,%1,%2,%3};"
                 : "+f"(c[0]), "+f"(c[1]), "+f"(c[2]), "+f"(c[3])
                 : "r"(a[0]), "r"(a[1]), "r"(a[2]), "r"(a[3]), "r"(b0), "r"(b1));
}
// cp.async 16B with zero-fill when src_size==0.
static __device__ __forceinline__ void cpa16(unsigned saddr, const void* gptr, int src_size) {
    asm volatile("cp.async.ca.shared.global [%0], [%1], 16, %2;"
                 :: "r"(saddr), "l"(gptr), "r"(src_size));
}
static __device__ __forceinline__ void cpa_commit_wait() {
    asm volatile("cp.async.commit_group;");
    asm volatile("cp.async.wait_group 0;" ::: "memory");
}

// Static device scratch.
__device__ __half g_mean16[(size_t)MAXN * D];  // pre-scaled mean (fp16)
__device__ __half g_x16[(size_t)MAXN * D];
__device__ __half g_h16[(size_t)MAXN * D];
__device__ __half g_w1[64 * 128];              // pre-converted [Wl|Wr] layer 1, [j][128]
__device__ __half g_w2[64 * 128];              // layer 2
__device__ int    g_cnt[MAXN];
__device__ int    g_off[MAXN];
__device__ int    g_srcs[MAXE];
__device__ int    g_chunksum[128];
__device__ int    g_chunkbase[128];
__device__ int    g_done;
__device__ float  g_rbc[64];       // 1/max(count(batch==b),1)

// ---------------------------------------------------------------------------
// k0: zero histogram/flags/pool output, pre-convert W1/W2 to fp16, rbc.
// ---------------------------------------------------------------------------
__global__ __launch_bounds__(256) void zero_kernel(int n_pad, float* __restrict__ out,
                                                   int n_out, const int* __restrict__ batch,
                                                   int N,
                                                   const float4* __restrict__ W1l4,
                                                   const float4* __restrict__ W1r4,
                                                   const float4* __restrict__ W2l4,
                                                   const float4* __restrict__ W2r4) {
    int i = blockIdx.x * 256 + threadIdx.x;
    if (i < n_pad) g_cnt[i] = 0;
    if (i < n_out) out[i] = 0.f;
    if (i == 0) g_done = 0;
    if (i < 4096) {
        int layer = i >> 11;            // 0: W1, 1: W2
        int ii = i & 2047;
        int half2nd = (ii >= 1024);
        int jj = ii & 1023;
        int j = jj >> 4, kq = jj & 15;  // row j, float4 index kq
        const float4* srcm = layer ? (half2nd ? W2r4 : W2l4)
                                   : (half2nd ? W1r4 : W1l4);
        float4 v = __ldg(&srcm[j * 16 + kq]);
        uint2 p;
        p.x = pack_h2(v.x, v.y);
        p.y = pack_h2(v.z, v.w);
        __half* dst = layer ? g_w2 : g_w1;
        *reinterpret_cast<uint2*>(&dst[j * 128 + half2nd * 64 + kq * 4]) = p;
    }
    if (blockIdx.x == 0 && threadIdx.x < 64) {
        int b = threadIdx.x;
        int lo0 = 0, hi = N;
        while (lo0 < hi) { int mid = (lo0 + hi) >> 1; if (__ldg(&batch[mid]) < b) lo0 = mid + 1; else hi = mid; }
        int lo1 = lo0; hi = N;
        while (lo1 < hi) { int mid = (lo1 + hi) >> 1; if (__ldg(&batch[mid]) < b + 1) lo1 = mid + 1; else hi = mid; }
        g_rbc[b] = 1.0f / fmaxf((float)(lo1 - lo0), 1.0f);
    }
}

// ---------------------------------------------------------------------------
// k1: in-degree histogram over dst (int4 loads) FUSED with x -> fp16 convert.
// ---------------------------------------------------------------------------
__global__ __launch_bounds__(256) void hist_conv_kernel(const int* __restrict__ dst, int E,
                                                        const float4* __restrict__ x4,
                                                        int n4) {
    int i = blockIdx.x * 256 + threadIdx.x;
    int hq = (E + 3) >> 2;
    if (i < hq) {
        int e = i * 4;
        if (e + 4 <= E) {
            int4 d = __ldg(reinterpret_cast<const int4*>(dst) + i);
            atomicAdd(&g_cnt[d.x], 1);
            atomicAdd(&g_cnt[d.y], 1);
            atomicAdd(&g_cnt[d.z], 1);
            atomicAdd(&g_cnt[d.w], 1);
        } else {
            for (; e < E; e++) atomicAdd(&g_cnt[__ldg(&dst[e])], 1);
        }
    }
    if (i < n4) {
        float4 v = __ldg(&x4[i]);
        uint2 p;
        p.x = pack_h2(v.x, v.y);
        p.y = pack_h2(v.z, v.w);
        reinterpret_cast<uint2*>(g_x16)[i] = p;
    }
}

// ---------------------------------------------------------------------------
// k2: per-chunk (1024) exclusive scan of g_cnt -> g_off (chunk-local); last
// block scans the chunk totals into g_chunkbase (decoupled via g_done).
// ---------------------------------------------------------------------------
__global__ __launch_bounds__(256) void scan_chunk_kernel() {
    __shared__ int w[256];
    __shared__ int isLast;
    int t = threadIdx.x;
    int base = blockIdx.x * CHUNK + t * 4;
    int4 c = *reinterpret_cast<const int4*>(&g_cnt[base]);
    int s0 = c.x, s1 = s0 + c.y, s2 = s1 + c.z, s3 = s2 + c.w;
    w[t] = s3;
    __syncthreads();
#pragma unroll
    for (int off = 1; off < 256; off <<= 1) {
        int v = (t >= off) ? w[t - off] : 0;
        __syncthreads();
        w[t] += v;
        __syncthreads();
    }
    int excl = (t > 0) ? w[t - 1] : 0;
    int4 o;
    o.x = excl; o.y = excl + s0; o.z = excl + s1; o.w = excl + s2;
    *reinterpret_cast<int4*>(&g_off[base]) = o;
    if (t == 255) g_chunksum[blockIdx.x] = w[255];

    __threadfence();
    if (t == 0) isLast = (atomicAdd(&g_done, 1) == (int)gridDim.x - 1);
    __syncthreads();
    if (isLast) {
        int v = 0;
        if (t < 128 && t < (int)gridDim.x)
            v = *((volatile int*)&g_chunksum[t]);
        if (t < 128) w[t] = v;
        __syncthreads();
#pragma unroll
        for (int off = 1; off < 128; off <<= 1) {
            int u = 0;
            if (t < 128 && t >= off) u = w[t - off];
            __syncthreads();
            if (t < 128) w[t] += u;
            __syncthreads();
        }
        if (t < 128) g_chunkbase[t] = (t > 0) ? w[t - 1] : 0;
    }
}

// ---------------------------------------------------------------------------
// k3: fill dst-sorted src list (scalar; latency-bound, max occupancy).
// ---------------------------------------------------------------------------
__global__ __launch_bounds__(256) void fill_kernel(const int* __restrict__ src,
                                                   const int* __restrict__ dst, int E) {
    int e = blockIdx.x * 256 + threadIdx.x;
    if (e >= E) return;
    int d = __ldg(&dst[e]);
    int p = atomicAdd(&g_off[d], 1) + __ldg(&g_chunkbase[d >> 10]);
    g_srcs[p] = __ldg(&src[e]);
}

// ---------------------------------------------------------------------------
// Gather aggregation (fp16 payload): 8 threads per dst node, shuffle-broadcast
// edge indices, fp32 accumulation, writes PRE-SCALED fp16 mean.
// ---------------------------------------------------------------------------
__global__ __launch_bounds__(256) void agg_kernel(const __half* __restrict__ feat, int N) {
    int g = blockIdx.x * 32 + (threadIdx.x >> 3);
    int lane = threadIdx.x & 7;
    unsigned gmask = 0xFFu << ((threadIdx.x & 31) & ~7);
    bool active = (g < N);
    int cnt = active ? g_cnt[g] : 0;
    int start = active ? (g_off[g] + __ldg(&g_chunkbase[g >> 10]) - cnt) : 0;
    const uint4* f4 = reinterpret_cast<const uint4*>(feat);
    float a[8];
#pragma unroll
    for (int c = 0; c < 8; c++) a[c] = 0.f;

    for (int i = 0; i < cnt; i += 8) {
        int my = (i + lane < cnt) ? __ldg(&g_srcs[start + i + lane]) : 0;
        int lim = cnt - i;
#pragma unroll
        for (int e = 0; e < 8; e++) {
            if (e >= lim) break;
            int s = __shfl_sync(gmask, my, e, 8);
            uint4 v = __ldg(f4 + (size_t)s * 8 + lane);
            float2 f0 = __half22float2(*reinterpret_cast<__half2*>(&v.x));
            float2 f1 = __half22float2(*reinterpret_cast<__half2*>(&v.y));
            float2 f2 = __half22float2(*reinterpret_cast<__half2*>(&v.z));
            float2 f3 = __half22float2(*reinterpret_cast<__half2*>(&v.w));
            a[0] += f0.x; a[1] += f0.y; a[2] += f1.x; a[3] += f1.y;
            a[4] += f2.x; a[5] += f2.y; a[6] += f3.x; a[7] += f3.y;
        }
    }
    if (active) {
        float r = 1.0f / fmaxf((float)cnt, 1.0f);
        uint4 pk;
        pk.x = pack_h2(a[0] * r, a[1] * r);
        pk.y = pack_h2(a[2] * r, a[3] * r);
        pk.z = pack_h2(a[4] * r, a[5] * r);
        pk.w = pack_h2(a[6] * r, a[7] * r);
        reinterpret_cast<uint4*>(g_mean16)[(size_t)g * 8 + lane] = pk;
    }
}

// ---------------------------------------------------------------------------
// Tensor-core SAGE layer with cp.async staging and smem-staged epilogue.
// out = act( [mean|x] @ [Wl|Wr]^T + b ), Wc pre-converted fp16 [j][128].
// ---------------------------------------------------------------------------
__global__ __launch_bounds__(256) void sage_kernel(const __half* __restrict__ xin16,
                                                   const __half* __restrict__ Wc,
                                                   const float* __restrict__ bl,
                                                   __half* __restrict__ hout16,
                                                   const int* __restrict__ batch,
                                                   float* __restrict__ pool_out,
                                                   int N, int do_pool) {
    extern __shared__ char smraw[];
    __half* sA   = reinterpret_cast<__half*>(smraw);                 // 128 x PAH halves
    __half* sW   = sA + 128 * PAH;                                   // 64 x PAH halves
    float*  sRbc = reinterpret_cast<float*>(sW + 64 * PAH);          // 64
    int*    sBat = reinterpret_cast<int*>(sRbc + 64);                // 128
    float*  pb   = reinterpret_cast<float*>(smraw);                  // pool reuse: 128 x PB

    const int tid  = threadIdx.x;
    const int base = blockIdx.x * BN;
    unsigned sAb = (unsigned)__cvta_generic_to_shared(sA);
    unsigned sWb = (unsigned)__cvta_generic_to_shared(sW);

    // --- async staging ---
    // A' = [mean16 | x16]: 2048 chunks of 16B (128 rows x 16 chunks).
#pragma unroll
    for (int r = 0; r < 8; r++) {
        int i = r * 256 + tid;
        int half2nd = (i >= BN * 8);
        int ii = i - half2nd * BN * 8;
        int n = ii >> 3, q = ii & 7;
        int node = base + n;
        const __half* srcbuf = half2nd ? xin16 : g_mean16;
        const void* gp = srcbuf + ((size_t)(node < N ? node : 0) * 64 + q * 8);
        cpa16(sAb + (unsigned)((n * PAH + half2nd * 64 + q * 8) * 2), gp,
              (node < N) ? 16 : 0);
    }
    // W': 1024 chunks of 16B (64 rows x 16 chunks of the 128-half row).
#pragma unroll
    for (int r = 0; r < 4; r++) {
        int c = r * 256 + tid;
        int j = c >> 4, q = c & 15;
        cpa16(sWb + (unsigned)((j * PAH + q * 8) * 2), Wc + j * 128 + q * 8, 16);
    }

    if (do_pool) {
        if (tid < BN) {
            int node = base + tid;
            sBat[tid] = (node < N) ? __ldg(&batch[node]) : 0;
        }
        if (tid >= BN && tid < BN + 64) sRbc[tid - BN] = g_rbc[tid - BN];
    }

    cpa_commit_wait();
    __syncthreads();

    const int l  = tid & 31;
    const int w  = tid >> 5;
    const int m0 = w * 16;

    unsigned aAddr = sAb + (unsigned)((m0 + (l & 15)) * (PAH * 2) + (l >> 4) * 16);
    unsigned bAddr = sWb + (unsigned)((((l & 7) + ((l >> 4) << 3)) * (PAH * 2)) + ((l >> 3) & 1) * 16);

    float acc[8][4];
#pragma unroll
    for (int nt = 0; nt < 8; nt++)
#pragma unroll
        for (int c = 0; c < 4; c++) acc[nt][c] = 0.f;

#pragma unroll
    for (int ks = 0; ks < 8; ks++) {
        unsigned a[4];
        ldsm4(a, aAddr + ks * 32);
#pragma unroll
        for (int np = 0; np < 4; np++) {
            unsigned t[4];
            ldsm4(t, bAddr + np * (16 * PAH * 2) + ks * 32);
            mma16816(acc[2 * np],     a, t[0], t[1]);
            mma16816(acc[2 * np + 1], a, t[2], t[3]);
        }
    }

    const int c2 = (l & 3) * 2;
    const int r0 = m0 + (l >> 2);
    const int r1 = r0 + 8;

    if (!do_pool) {
        // Smem-staged epilogue: fragment-order 4B smem writes (conflict-free),
        // then fully-coalesced uint4 gmem stores.
        __syncthreads();  // all warps done reading sA via ldsm
#pragma unroll
        for (int nt = 0; nt < 8; nt++) {
            int col = nt * 8 + c2;
            float b0 = __ldg(&bl[col]), b1 = __ldg(&bl[col + 1]);
            *reinterpret_cast<unsigned*>(&sA[r0 * PAH + col]) =
                pack_h2(fmaxf(acc[nt][0] + b0, 0.f), fmaxf(acc[nt][1] + b1, 0.f));
            *reinterpret_cast<unsigned*>(&sA[r1 * PAH + col]) =
                pack_h2(fmaxf(acc[nt][2] + b0, 0.f), fmaxf(acc[nt][3] + b1, 0.f));
        }
        __syncthreads();
        // 128 rows x 8 uint4 = 1024 stores; 4 per thread, coalesced in gmem.
#pragma unroll
        for (int r = 0; r < 4; r++) {
            int i = r * 256 + tid;
            int n = i >> 3, q = i & 7;
            int node = base + n;
            if (node < N) {
                uint4 v = *reinterpret_cast<const uint4*>(&sA[n * PAH + q * 8]);
                reinterpret_cast<uint4*>(hout16)[(size_t)node * 8 + q] = v;
            }
        }
    } else {
        __syncthreads();  // done with sA region; reuse as pool buffer
#pragma unroll
        for (int nt = 0; nt < 8; nt++) {
            int col = nt * 8 + c2;
            float b0 = __ldg(&bl[col]), b1 = __ldg(&bl[col + 1]);
            float2 v0, v1;
            v0.x = (base + r0 < N) ? acc[nt][0] + b0 : 0.f;
            v0.y = (base + r0 < N) ? acc[nt][1] + b1 : 0.f;
            v1.x = (base + r1 < N) ? acc[nt][2] + b0 : 0.f;
            v1.y = (base + r1 < N) ? acc[nt][3] + b1 : 0.f;
            *reinterpret_cast<float2*>(&pb[r0 * PB + col]) = v0;
            *reinterpret_cast<float2*>(&pb[r1 * PB + col]) = v1;
        }
        __syncthreads();
        if (tid < 64) {
            const int j = tid;
            int cur = sBat[0];
            float sum = 0.f;
#pragma unroll 4
            for (int n = 0; n < BN; n++) {
                int b = sBat[n];
                if (b != cur) {
                    atomicAdd(&pool_out[cur * 64 + j], sum * sRbc[cur]);
                    sum = 0.f;
                    cur = b;
                }
                sum += pb[n * PB + j];
            }
            atomicAdd(&pool_out[cur * 64 + j], sum * sRbc[cur]);
        }
    }
}

// ---------------------------------------------------------------------------
// kernel_launch
// Inputs: x, edge_index, edge_attr, batch, edge_emb,
//         W1_l, b1_l, W1_r, W2_l, b2_l, W2_r
// ---------------------------------------------------------------------------
extern "C" void kernel_launch(void* const* d_in, const int* in_sizes, int n_in,
                              void* d_out, int out_size) {
    const float* x     = (const float*)d_in[0];
    const int*   eidx  = (const int*)d_in[1];
    const int*   batch = (const int*)d_in[3];
    const float* W1l   = (const float*)d_in[5];
    const float* b1l   = (const float*)d_in[6];
    const float* W1r   = (const float*)d_in[7];
    const float* W2l   = (const float*)d_in[8];
    const float* b2l   = (const float*)d_in[9];
    const float* W2r   = (const float*)d_in[10];
    float*       out   = (float*)d_out;

    const int N = in_sizes[3];
    const int E = in_sizes[1] / 2;
    const int* src = eidx;
    const int* dst = eidx + E;

    void* xp = nullptr; void* hp = nullptr; void* w1p = nullptr; void* w2p = nullptr;
    cudaGetSymbolAddress(&xp, g_x16);
    cudaGetSymbolAddress(&hp, g_h16);
    cudaGetSymbolAddress(&w1p, g_w1);
    cudaGetSymbolAddress(&w2p, g_w2);
    __half* x16 = (__half*)xp;
    __half* h16 = (__half*)hp;
    __half* w1c = (__half*)w1p;
    __half* w2c = (__half*)w2p;

    const int smem = (128 + 64) * PAH * (int)sizeof(__half)
                     + 64 * (int)sizeof(float) + BN * (int)sizeof(int);
    cudaFuncSetAttribute(sage_kernel, cudaFuncAttributeMaxDynamicSharedMemorySize, smem);

    const int nchunk = (N + CHUNK - 1) / CHUNK;
    const int n_pad  = nchunk * CHUNK;
    const int n4     = N * 16;
    const int zb     = (n_pad + 255) / 256;
    const int hq     = (E + 3) / 4;
    const int hcb    = (max(hq, n4) + 255) / 256;
    const int eblk   = (E + 255) / 256;
    const int ablk   = (N + 31) / 32;
    const int gblk   = (N + BN - 1) / BN;

    // CSR build + conversions (once; reused by both layers)
    zero_kernel<<<zb, 256>>>(n_pad, out, out_size, batch, N,
                             reinterpret_cast<const float4*>(W1l),
                             reinterpret_cast<const float4*>(W1r),
                             reinterpret_cast<const float4*>(W2l),
                             reinterpret_cast<const float4*>(W2r));
    hist_conv_kernel<<<hcb, 256>>>(dst, E, reinterpret_cast<const float4*>(x), n4);
    scan_chunk_kernel<<<nchunk, 256>>>();
    fill_kernel<<<eblk, 256>>>(src, dst, E);

    // Layer 1
    agg_kernel<<<ablk, 256>>>(x16, N);
    sage_kernel<<<gblk, 256, smem>>>(x16, w1c, b1l, h16, nullptr, nullptr, N, 0);

    // Layer 2 + fused scaled pool
    agg_kernel<<<ablk, 256>>>(h16, N);
    sage_kernel<<<gblk, 256, smem>>>(h16, w2c, b2l, nullptr, batch, out, N, 1);
}